// round 1
// baseline (speedup 1.0000x reference)
#include <cuda_runtime.h>
#include <math.h>

#define B_  8
#define TQ_ 1024
#define TK_ 1024
#define D_  1024
#define H_  16
#define HD_ 64

// ---------------- scratch (static device memory; no allocs allowed) -----------
__device__ float g_q [B_*TQ_*D_];               // Q proj -> later Wo-proj -> later y
__device__ float g_k [B_*TK_*D_];               // K proj -> later h1
__device__ float g_v [B_*TK_*D_];               // V proj -> later ff
__device__ float g_sc[134217728];               // scores -> attn2 (in place), 512MB
__device__ float g_ao[B_*TQ_*D_];               // merged-head attention output
__device__ float g_x [B_*TQ_*D_];               // x after LN1

// ---------------- reductions --------------------------------------------------
__device__ __forceinline__ float warpRedMax(float v) {
#pragma unroll
    for (int o = 16; o > 0; o >>= 1) v = fmaxf(v, __shfl_xor_sync(0xffffffffu, v, o));
    return v;
}
__device__ __forceinline__ float warpRedSum(float v) {
#pragma unroll
    for (int o = 16; o > 0; o >>= 1) v += __shfl_xor_sync(0xffffffffu, v, o);
    return v;
}
__device__ __forceinline__ float blockRedMax(float v, float* red) {
    v = warpRedMax(v);
    if ((threadIdx.x & 31) == 0) red[threadIdx.x >> 5] = v;
    __syncthreads();
    if (threadIdx.x < 32) {
        float x = (threadIdx.x < (blockDim.x >> 5)) ? red[threadIdx.x] : -3.4e38f;
        x = warpRedMax(x);
        if (threadIdx.x == 0) red[0] = x;
    }
    __syncthreads();
    float r = red[0];
    __syncthreads();
    return r;
}
__device__ __forceinline__ float blockRedSum(float v, float* red) {
    v = warpRedSum(v);
    if ((threadIdx.x & 31) == 0) red[threadIdx.x >> 5] = v;
    __syncthreads();
    if (threadIdx.x < 32) {
        float x = (threadIdx.x < (blockDim.x >> 5)) ? red[threadIdx.x] : 0.f;
        x = warpRedSum(x);
        if (threadIdx.x == 0) red[0] = x;
    }
    __syncthreads();
    float r = red[0];
    __syncthreads();
    return r;
}

// ---------------- GEMM: C = alpha * A @ B^T (+bias)(+silu) --------------------
// A:[M,K] lda, B:[N,K] ldb, C:[M,N] ldc. Tiles 128x128x8, 256 thr, 8x8/thread.
// Batched-head offsets: z -> (z/16)*s?1 + (z%16)*s?2  (H_=16 hardcoded).
// M,N multiples of 128, K multiple of 8 (all shapes here comply).
__global__ void __launch_bounds__(256)
gemm_nt_k(const float* __restrict__ A, const float* __restrict__ Bm,
          float* __restrict__ C, int Kd, int lda, int ldb, int ldc,
          long sA1, long sA2, long sB1, long sB2, long sC1, long sC2,
          float alpha, const float* __restrict__ bias, int mode)
{
    const int z = blockIdx.z;
    const long zb = z >> 4, zh = z & 15;
    const float* Ab = A  + zb * sA1 + zh * sA2;
    const float* Bb = Bm + zb * sB1 + zh * sB2;
    float*       Cb = C  + zb * sC1 + zh * sC2;

    __shared__ float As[8][128];
    __shared__ float Bs[8][128];

    const int tid  = threadIdx.x;
    const int m0   = blockIdx.y * 128;
    const int n0   = blockIdx.x * 128;
    const int lrow = tid >> 1;          // 0..127
    const int lk   = (tid & 1) * 4;     // 0 or 4
    const int ty   = tid >> 4;          // 0..15
    const int tx   = tid & 15;          // 0..15

    float acc[8][8];
#pragma unroll
    for (int i = 0; i < 8; i++)
#pragma unroll
        for (int j = 0; j < 8; j++) acc[i][j] = 0.f;

    for (int k0 = 0; k0 < Kd; k0 += 8) {
        float4 av = *reinterpret_cast<const float4*>(&Ab[(long)(m0 + lrow) * lda + k0 + lk]);
        float4 bv = *reinterpret_cast<const float4*>(&Bb[(long)(n0 + lrow) * ldb + k0 + lk]);
        As[lk + 0][lrow] = av.x; As[lk + 1][lrow] = av.y;
        As[lk + 2][lrow] = av.z; As[lk + 3][lrow] = av.w;
        Bs[lk + 0][lrow] = bv.x; Bs[lk + 1][lrow] = bv.y;
        Bs[lk + 2][lrow] = bv.z; Bs[lk + 3][lrow] = bv.w;
        __syncthreads();
#pragma unroll
        for (int kk = 0; kk < 8; kk++) {
            float ra[8], rb[8];
#pragma unroll
            for (int i = 0; i < 8; i++) ra[i] = As[kk][ty * 8 + i];
#pragma unroll
            for (int j = 0; j < 8; j++) rb[j] = Bs[kk][tx * 8 + j];
#pragma unroll
            for (int i = 0; i < 8; i++)
#pragma unroll
                for (int j = 0; j < 8; j++)
                    acc[i][j] = fmaf(ra[i], rb[j], acc[i][j]);
        }
        __syncthreads();
    }

#pragma unroll
    for (int i = 0; i < 8; i++) {
        const long m = m0 + ty * 8 + i;
        float o[8];
#pragma unroll
        for (int j = 0; j < 8; j++) {
            const int n = n0 + tx * 8 + j;
            float v = acc[i][j] * alpha;
            if (mode >= 1) v += bias[n];
            if (mode == 2) v = v * (1.f / (1.f + expf(-v)));   // SiLU
            o[j] = v;
        }
        float4* cp = reinterpret_cast<float4*>(&Cb[m * ldc + n0 + tx * 8]);
        cp[0] = make_float4(o[0], o[1], o[2], o[3]);
        cp[1] = make_float4(o[4], o[5], o[6], o[7]);
    }
}

// ---------------- attn2 @ V  (NN, N=64, per (b,h)) ----------------------------
// C[q, h*64+d] = sum_k attn2_bh[q,k] * V_bh[k,d]; writes merged-head layout.
__global__ void __launch_bounds__(256)
attn_v_k(const float* __restrict__ A2, const float* __restrict__ Vp,
         float* __restrict__ C)
{
    const int z  = blockIdx.z;            // b*H + h
    const long zb = z >> 4, zh = z & 15;
    const float* Ab = A2 + (long)z * ((long)TQ_ * TK_);
    const float* Bb = Vp + zb * ((long)TK_ * D_) + zh * HD_;
    float*       Cb = C  + zb * ((long)TQ_ * D_) + zh * HD_;
    const int m0 = blockIdx.y * 64;

    __shared__ float As[16][64];
    __shared__ float Bs[16][64];

    const int tid  = threadIdx.x;
    const int arow = tid >> 2;            // 0..63
    const int ak   = (tid & 3) * 4;       // 0,4,8,12
    const int bk   = tid >> 4;            // 0..15
    const int bn   = (tid & 15) * 4;      // 0..60
    const int ty   = tid >> 4;            // 0..15
    const int tx   = tid & 15;            // 0..15

    float acc[4][4];
#pragma unroll
    for (int i = 0; i < 4; i++)
#pragma unroll
        for (int j = 0; j < 4; j++) acc[i][j] = 0.f;

    for (int k0 = 0; k0 < TK_; k0 += 16) {
        float4 av = *reinterpret_cast<const float4*>(&Ab[(long)(m0 + arow) * TK_ + k0 + ak]);
        As[ak + 0][arow] = av.x; As[ak + 1][arow] = av.y;
        As[ak + 2][arow] = av.z; As[ak + 3][arow] = av.w;
        float4 bv = *reinterpret_cast<const float4*>(&Bb[(long)(k0 + bk) * D_ + bn]);
        *reinterpret_cast<float4*>(&Bs[bk][bn]) = bv;
        __syncthreads();
#pragma unroll
        for (int kk = 0; kk < 16; kk++) {
            float ra[4], rb[4];
#pragma unroll
            for (int i = 0; i < 4; i++) ra[i] = As[kk][ty * 4 + i];
#pragma unroll
            for (int j = 0; j < 4; j++) rb[j] = Bs[kk][tx * 4 + j];
#pragma unroll
            for (int i = 0; i < 4; i++)
#pragma unroll
                for (int j = 0; j < 4; j++)
                    acc[i][j] = fmaf(ra[i], rb[j], acc[i][j]);
        }
        __syncthreads();
    }
#pragma unroll
    for (int i = 0; i < 4; i++) {
        const long m = m0 + ty * 4 + i;
        *reinterpret_cast<float4*>(&Cb[m * D_ + tx * 4]) =
            make_float4(acc[i][0], acc[i][1], acc[i][2], acc[i][3]);
    }
}

// ---------------- softmax -> threshold mask -> softmax2 (per row) -------------
// Row = 1024 f32. Writes masked to out, attn2 in-place over scores.
__global__ void __launch_bounds__(256)
softmax_mask_k(float* __restrict__ scores, float* __restrict__ masked,
               const float* __restrict__ alphap)
{
    __shared__ float red[32];
    const long row = blockIdx.x;
    float4* srow = reinterpret_cast<float4*>(scores + row * 1024);
    float4* mrow = reinterpret_cast<float4*>(masked + row * 1024);
    const int tid = threadIdx.x;
    const float alpha = *alphap;

    float4 v4 = srow[tid];
    float v[4] = {v4.x, v4.y, v4.z, v4.w};

    float mx = fmaxf(fmaxf(v[0], v[1]), fmaxf(v[2], v[3]));
    mx = blockRedMax(mx, red);

    float e[4], s = 0.f;
#pragma unroll
    for (int i = 0; i < 4; i++) { e[i] = expf(v[i] - mx); s += e[i]; }
    s = blockRedSum(s, red);
    const float inv = 1.f / s;

    float mk[4];
#pragma unroll
    for (int i = 0; i < 4; i++) {
        float a = e[i] * inv;
        mk[i] = (a >= alpha) ? a : 0.f;
    }
    mrow[tid] = make_float4(mk[0], mk[1], mk[2], mk[3]);

    float mx2 = fmaxf(fmaxf(mk[0], mk[1]), fmaxf(mk[2], mk[3]));
    mx2 = blockRedMax(mx2, red);

    float e2[4], s2 = 0.f;
#pragma unroll
    for (int i = 0; i < 4; i++) { e2[i] = expf(mk[i] - mx2); s2 += e2[i]; }
    s2 = blockRedSum(s2, red);
    const float inv2 = 1.f / s2;

    srow[tid] = make_float4(e2[0] * inv2, e2[1] * inv2, e2[2] * inv2, e2[3] * inv2);
}

// ---------------- out = LayerNorm(a + b) * g + beta ---------------------------
__global__ void __launch_bounds__(256)
add_ln_k(const float* __restrict__ A, const float* __restrict__ Bsrc,
         const float* __restrict__ g, const float* __restrict__ bet,
         float* __restrict__ out)
{
    __shared__ float red[32];
    const long row = blockIdx.x;
    const int tid = threadIdx.x;

    float4 a4 = reinterpret_cast<const float4*>(A    + row * 1024)[tid];
    float4 b4 = reinterpret_cast<const float4*>(Bsrc + row * 1024)[tid];
    float x[4] = {a4.x + b4.x, a4.y + b4.y, a4.z + b4.z, a4.w + b4.w};

    float s = x[0] + x[1] + x[2] + x[3];
    s = blockRedSum(s, red);
    const float mu = s * (1.f / 1024.f);

    float vs = 0.f;
#pragma unroll
    for (int i = 0; i < 4; i++) { float d = x[i] - mu; vs += d * d; }
    vs = blockRedSum(vs, red);
    const float inv = rsqrtf(vs * (1.f / 1024.f) + 1e-5f);

    float4 g4 = reinterpret_cast<const float4*>(g)[tid];
    float4 e4 = reinterpret_cast<const float4*>(bet)[tid];
    float4 o;
    o.x = (x[0] - mu) * inv * g4.x + e4.x;
    o.y = (x[1] - mu) * inv * g4.y + e4.y;
    o.z = (x[2] - mu) * inv * g4.z + e4.z;
    o.w = (x[3] - mu) * inv * g4.w + e4.w;
    reinterpret_cast<float4*>(out + row * 1024)[tid] = o;
}

// ---------------- driver ------------------------------------------------------
extern "C" void kernel_launch(void* const* d_in, const int* in_sizes, int n_in,
                              void* d_out, int out_size)
{
    const float* base   = (const float*)d_in[0];
    const float* fusion = (const float*)d_in[1];
    const float* Wq     = (const float*)d_in[2];
    const float* Wk     = (const float*)d_in[3];
    const float* Wv     = (const float*)d_in[4];
    const float* Wo     = (const float*)d_in[5];
    const float* g1     = (const float*)d_in[6];
    const float* b1     = (const float*)d_in[7];
    const float* g2     = (const float*)d_in[8];
    const float* b2     = (const float*)d_in[9];
    const float* fc1_w  = (const float*)d_in[10];
    const float* fc1_b  = (const float*)d_in[11];
    const float* fc2_w  = (const float*)d_in[12];
    const float* fc2_b  = (const float*)d_in[13];
    const float* rw     = (const float*)d_in[14];
    const float* rbias  = (const float*)d_in[15];
    const float* alphap = (const float*)d_in[16];

    float* outf = (float*)d_out;                       // final [8,1024,1024]
    float* outm = outf + (long)B_ * TQ_ * D_;          // masked [8,16,1024,1024]

    float *q, *k, *v, *sc, *ao, *x;
    cudaGetSymbolAddress((void**)&q,  g_q);
    cudaGetSymbolAddress((void**)&k,  g_k);
    cudaGetSymbolAddress((void**)&v,  g_v);
    cudaGetSymbolAddress((void**)&sc, g_sc);
    cudaGetSymbolAddress((void**)&ao, g_ao);
    cudaGetSymbolAddress((void**)&x,  g_x);

    const dim3 blk(256);
    const dim3 gBig(D_ / 128, (B_ * TQ_) / 128, 1);    // 8 x 64

    // Q/K/V projections
    gemm_nt_k<<<gBig, blk>>>(base,   Wq, q, D_, D_, D_, D_, 0,0,0,0,0,0, 1.f, nullptr, 0);
    gemm_nt_k<<<gBig, blk>>>(fusion, Wk, k, D_, D_, D_, D_, 0,0,0,0,0,0, 1.f, nullptr, 0);
    gemm_nt_k<<<gBig, blk>>>(fusion, Wv, v, D_, D_, D_, D_, 0,0,0,0,0,0, 1.f, nullptr, 0);

    // scores = Q K^T / sqrt(HD)  per (b,h)
    gemm_nt_k<<<dim3(TK_ / 128, TQ_ / 128, B_ * H_), blk>>>(
        q, k, sc, HD_, D_, D_, TK_,
        (long)TQ_ * D_, HD_, (long)TK_ * D_, HD_,
        (long)H_ * TQ_ * TK_, (long)TQ_ * TK_,
        0.125f, nullptr, 0);

    // softmax -> mask (write masked output) -> softmax2 (in place)
    softmax_mask_k<<<B_ * H_ * TQ_, blk>>>(sc, outm, alphap);

    // attn2 @ V -> merged heads
    attn_v_k<<<dim3(1, TQ_ / 64, B_ * H_), blk>>>(sc, v, ao);

    // O projection (reuse g_q)
    gemm_nt_k<<<gBig, blk>>>(ao, Wo, q, D_, D_, D_, D_, 0,0,0,0,0,0, 1.f, nullptr, 0);

    // x = LN(base + proj)
    add_ln_k<<<B_ * TQ_, blk>>>(base, q, g1, b1, x);

    // FFN: h1 = silu(x fc1^T + b)  (reuse g_k), ff = silu(h1 fc2^T + b) (reuse g_v)
    gemm_nt_k<<<gBig, blk>>>(x, fc1_w, k, D_, D_, D_, D_, 0,0,0,0,0,0, 1.f, fc1_b, 2);
    gemm_nt_k<<<gBig, blk>>>(k, fc2_w, v, D_, D_, D_, D_, 0,0,0,0,0,0, 1.f, fc2_b, 2);

    // y = LN(x + ff)  (reuse g_q)
    add_ln_k<<<B_ * TQ_, blk>>>(x, v, g2, b2, q);

    // final = y rw^T + rb
    gemm_nt_k<<<gBig, blk>>>(q, rw, outf, D_, D_, D_, D_, 0,0,0,0,0,0, 1.f, rbias, 1);
}

// round 2
// speedup vs baseline: 2.7105x; 2.7105x over previous
#include <cuda_runtime.h>
#include <math.h>
#include <stdint.h>

#define B_  8
#define TQ_ 1024
#define TK_ 1024
#define D_  1024
#define H_  16
#define HD_ 64

// ---------------- scratch (static device memory; no allocs allowed) -----------
__device__ float g_q [B_*TQ_*D_];               // Q proj -> later Wo-proj -> later y
__device__ float g_k [B_*TK_*D_];               // K proj -> later h1
__device__ float g_v [B_*TK_*D_];               // V proj -> later ff
__device__ float g_sc[134217728];               // scores -> attn2 (in place)
__device__ float g_ao[B_*TQ_*D_];               // merged-head attention output
__device__ float g_x [B_*TQ_*D_];               // x after LN1

// ---------------- tf32 helpers ------------------------------------------------
__device__ __forceinline__ uint32_t f2tf32(float x) {
    uint32_t r;
    asm("cvt.rna.tf32.f32 %0, %1;" : "=r"(r) : "f"(x));
    return r;
}

__device__ __forceinline__ void mma_tf32(float* c,
                                         uint32_t a0, uint32_t a1, uint32_t a2, uint32_t a3,
                                         uint32_t b0, uint32_t b1) {
    asm volatile(
        "mma.sync.aligned.m16n8k8.row.col.f32.tf32.tf32.f32 "
        "{%0,%1,%2,%3}, {%4,%5,%6,%7}, {%8,%9}, {%0,%1,%2,%3};"
        : "+f"(c[0]), "+f"(c[1]), "+f"(c[2]), "+f"(c[3])
        : "r"(a0), "r"(a1), "r"(a2), "r"(a3), "r"(b0), "r"(b1));
}

// ---------------- reductions --------------------------------------------------
__device__ __forceinline__ float warpRedMax(float v) {
#pragma unroll
    for (int o = 16; o > 0; o >>= 1) v = fmaxf(v, __shfl_xor_sync(0xffffffffu, v, o));
    return v;
}
__device__ __forceinline__ float warpRedSum(float v) {
#pragma unroll
    for (int o = 16; o > 0; o >>= 1) v += __shfl_xor_sync(0xffffffffu, v, o);
    return v;
}
__device__ __forceinline__ float blockRedMax(float v, float* red) {
    v = warpRedMax(v);
    if ((threadIdx.x & 31) == 0) red[threadIdx.x >> 5] = v;
    __syncthreads();
    if (threadIdx.x < 32) {
        float x = (threadIdx.x < (blockDim.x >> 5)) ? red[threadIdx.x] : -3.4e38f;
        x = warpRedMax(x);
        if (threadIdx.x == 0) red[0] = x;
    }
    __syncthreads();
    float r = red[0];
    __syncthreads();
    return r;
}
__device__ __forceinline__ float blockRedSum(float v, float* red) {
    v = warpRedSum(v);
    if ((threadIdx.x & 31) == 0) red[threadIdx.x >> 5] = v;
    __syncthreads();
    if (threadIdx.x < 32) {
        float x = (threadIdx.x < (blockDim.x >> 5)) ? red[threadIdx.x] : 0.f;
        x = warpRedSum(x);
        if (threadIdx.x == 0) red[0] = x;
    }
    __syncthreads();
    float r = red[0];
    __syncthreads();
    return r;
}

// ============ TF32 GEMM: C = alpha * A @ B^T (+bias)(+silu) ===================
// A:[M,K] lda, B:[N,K] ldb, C:[M,N] ldc. Block tile 128x128x32, 256 thr.
// 8 warps: warpM = w&1 (2 x 64 rows), warpN = w>>1 (4 x 32 cols).
// Per warp: 4 m-tiles (16) x 4 n-tiles (8), mma.m16n8k8 tf32.
// Batched z: z -> (z>>4)*s?1 + (z&15)*s?2.
// Requires M,N mult of 128, K mult of 32... (K=64 here also fine: mult of 32).
__global__ void __launch_bounds__(256)
gemm_nt_tf32(const float* __restrict__ A, const float* __restrict__ Bm,
             float* __restrict__ C, int Kd, int lda, int ldb, int ldc,
             long sA1, long sA2, long sB1, long sB2, long sC1, long sC2,
             float alpha, const float* __restrict__ bias, int mode)
{
    const int z = blockIdx.z;
    const long zb = z >> 4, zh = z & 15;
    const float* Ab = A  + zb * sA1 + zh * sA2;
    const float* Bb = Bm + zb * sB1 + zh * sB2;
    float*       Cb = C  + zb * sC1 + zh * sC2;

    __shared__ uint32_t As[128][36];   // [row][k], pitch 36 -> bank (4r+k)&31
    __shared__ uint32_t Bs[128][36];   // [col][k]

    const int tid   = threadIdx.x;
    const int m0    = blockIdx.y * 128;
    const int n0    = blockIdx.x * 128;
    const int warp  = tid >> 5;
    const int lane  = tid & 31;
    const int warpM = warp & 1;
    const int warpN = warp >> 1;
    const int g     = lane >> 2;     // group id 0..7
    const int tg    = lane & 3;      // thread in group 0..3

    const int lr = tid >> 3;         // 0..31 (rows, +32*i)
    const int lc = (tid & 7) * 4;    // k offset 0..28

    float acc[4][4][4];
#pragma unroll
    for (int mt = 0; mt < 4; mt++)
#pragma unroll
        for (int nt = 0; nt < 4; nt++)
#pragma unroll
            for (int r = 0; r < 4; r++) acc[mt][nt][r] = 0.f;

    for (int k0 = 0; k0 < Kd; k0 += 32) {
#pragma unroll
        for (int i = 0; i < 4; i++) {
            const int r = lr + i * 32;
            float4 av = *reinterpret_cast<const float4*>(&Ab[(long)(m0 + r) * lda + k0 + lc]);
            As[r][lc + 0] = f2tf32(av.x); As[r][lc + 1] = f2tf32(av.y);
            As[r][lc + 2] = f2tf32(av.z); As[r][lc + 3] = f2tf32(av.w);
            float4 bv = *reinterpret_cast<const float4*>(&Bb[(long)(n0 + r) * ldb + k0 + lc]);
            Bs[r][lc + 0] = f2tf32(bv.x); Bs[r][lc + 1] = f2tf32(bv.y);
            Bs[r][lc + 2] = f2tf32(bv.z); Bs[r][lc + 3] = f2tf32(bv.w);
        }
        __syncthreads();

#pragma unroll
        for (int kk = 0; kk < 32; kk += 8) {
            uint32_t af[4][4], bf[4][2];
#pragma unroll
            for (int mt = 0; mt < 4; mt++) {
                const int row = warpM * 64 + mt * 16 + g;
                af[mt][0] = As[row    ][kk + tg];
                af[mt][1] = As[row + 8][kk + tg];
                af[mt][2] = As[row    ][kk + tg + 4];
                af[mt][3] = As[row + 8][kk + tg + 4];
            }
#pragma unroll
            for (int nt = 0; nt < 4; nt++) {
                const int col = warpN * 32 + nt * 8 + g;
                bf[nt][0] = Bs[col][kk + tg];
                bf[nt][1] = Bs[col][kk + tg + 4];
            }
#pragma unroll
            for (int mt = 0; mt < 4; mt++)
#pragma unroll
                for (int nt = 0; nt < 4; nt++)
                    mma_tf32(acc[mt][nt], af[mt][0], af[mt][1], af[mt][2], af[mt][3],
                             bf[nt][0], bf[nt][1]);
        }
        __syncthreads();
    }

    // epilogue: c0,c1 at (row, 2tg/2tg+1), c2,c3 at (row+8, ...)
#pragma unroll
    for (int mt = 0; mt < 4; mt++) {
#pragma unroll
        for (int nt = 0; nt < 4; nt++) {
            const long row = m0 + warpM * 64 + mt * 16 + g;
            const int  col = n0 + warpN * 32 + nt * 8 + 2 * tg;
            float v0 = acc[mt][nt][0] * alpha;
            float v1 = acc[mt][nt][1] * alpha;
            float v2 = acc[mt][nt][2] * alpha;
            float v3 = acc[mt][nt][3] * alpha;
            if (mode >= 1) {
                const float bb0 = bias[col], bb1 = bias[col + 1];
                v0 += bb0; v1 += bb1; v2 += bb0; v3 += bb1;
            }
            if (mode == 2) {
                v0 = v0 / (1.f + expf(-v0));
                v1 = v1 / (1.f + expf(-v1));
                v2 = v2 / (1.f + expf(-v2));
                v3 = v3 / (1.f + expf(-v3));
            }
            *reinterpret_cast<float2*>(&Cb[row * ldc + col])       = make_float2(v0, v1);
            *reinterpret_cast<float2*>(&Cb[(row + 8) * ldc + col]) = make_float2(v2, v3);
        }
    }
}

// ============ TF32 attn2 @ V (NN, N=64, per (b,h)) ============================
// C[q, h*64+d] = sum_k attn2_bh[q,k] * V_bh[k,d]. Block 128x64x32, 256 thr.
// 8 warps: warpM = w&3 (4 x 32 rows), warpN = w>>2 (2 x 32 cols).
__global__ void __launch_bounds__(256)
attn_v_tf32(const float* __restrict__ A2, const float* __restrict__ Vp,
            float* __restrict__ Cout)
{
    const int z  = blockIdx.z;
    const long zb = z >> 4, zh = z & 15;
    const float* Ab = A2 + (long)z * ((long)TQ_ * TK_);
    const float* Bb = Vp + zb * ((long)TK_ * D_) + zh * HD_;
    float*       Cb = Cout + zb * ((long)TQ_ * D_) + zh * HD_;
    const int m0 = blockIdx.y * 128;

    __shared__ uint32_t As[128][36];   // [row][k]
    __shared__ uint32_t Bs[64][36];    // [n][k] (transposed during load)

    const int tid   = threadIdx.x;
    const int warp  = tid >> 5;
    const int lane  = tid & 31;
    const int warpM = warp & 3;
    const int warpN = warp >> 2;
    const int g     = lane >> 2;
    const int tg    = lane & 3;

    const int lr = tid >> 3;
    const int lc = (tid & 7) * 4;

    float acc[2][4][4];
#pragma unroll
    for (int mt = 0; mt < 2; mt++)
#pragma unroll
        for (int nt = 0; nt < 4; nt++)
#pragma unroll
            for (int r = 0; r < 4; r++) acc[mt][nt][r] = 0.f;

    for (int k0 = 0; k0 < TK_; k0 += 32) {
#pragma unroll
        for (int i = 0; i < 4; i++) {
            const int r = lr + i * 32;
            float4 av = *reinterpret_cast<const float4*>(&Ab[(long)(m0 + r) * TK_ + k0 + lc]);
            As[r][lc + 0] = f2tf32(av.x); As[r][lc + 1] = f2tf32(av.y);
            As[r][lc + 2] = f2tf32(av.z); As[r][lc + 3] = f2tf32(av.w);
        }
        // V tile 32(k) x 64(n), transposed into Bs[n][k]
#pragma unroll
        for (int i = 0; i < 2; i++) {
            const int k = (tid >> 4) + i * 16;      // 0..31
            const int c = (tid & 15) * 4;           // 0..60
            float4 vv = *reinterpret_cast<const float4*>(&Bb[(long)(k0 + k) * D_ + c]);
            Bs[c + 0][k] = f2tf32(vv.x); Bs[c + 1][k] = f2tf32(vv.y);
            Bs[c + 2][k] = f2tf32(vv.z); Bs[c + 3][k] = f2tf32(vv.w);
        }
        __syncthreads();

#pragma unroll
        for (int kk = 0; kk < 32; kk += 8) {
            uint32_t af[2][4], bf[4][2];
#pragma unroll
            for (int mt = 0; mt < 2; mt++) {
                const int row = warpM * 32 + mt * 16 + g;
                af[mt][0] = As[row    ][kk + tg];
                af[mt][1] = As[row + 8][kk + tg];
                af[mt][2] = As[row    ][kk + tg + 4];
                af[mt][3] = As[row + 8][kk + tg + 4];
            }
#pragma unroll
            for (int nt = 0; nt < 4; nt++) {
                const int col = warpN * 32 + nt * 8 + g;
                bf[nt][0] = Bs[col][kk + tg];
                bf[nt][1] = Bs[col][kk + tg + 4];
            }
#pragma unroll
            for (int mt = 0; mt < 2; mt++)
#pragma unroll
                for (int nt = 0; nt < 4; nt++)
                    mma_tf32(acc[mt][nt], af[mt][0], af[mt][1], af[mt][2], af[mt][3],
                             bf[nt][0], bf[nt][1]);
        }
        __syncthreads();
    }

#pragma unroll
    for (int mt = 0; mt < 2; mt++) {
#pragma unroll
        for (int nt = 0; nt < 4; nt++) {
            const long row = m0 + warpM * 32 + mt * 16 + g;
            const int  col = warpN * 32 + nt * 8 + 2 * tg;
            *reinterpret_cast<float2*>(&Cb[row * D_ + col]) =
                make_float2(acc[mt][nt][0], acc[mt][nt][1]);
            *reinterpret_cast<float2*>(&Cb[(row + 8) * D_ + col]) =
                make_float2(acc[mt][nt][2], acc[mt][nt][3]);
        }
    }
}

// ---------------- softmax -> threshold mask -> softmax2 (per row) -------------
__global__ void __launch_bounds__(256)
softmax_mask_k(float* __restrict__ scores, float* __restrict__ masked,
               const float* __restrict__ alphap)
{
    __shared__ float red[32];
    const long row = blockIdx.x;
    float4* srow = reinterpret_cast<float4*>(scores + row * 1024);
    float4* mrow = reinterpret_cast<float4*>(masked + row * 1024);
    const int tid = threadIdx.x;
    const float alpha = *alphap;

    float4 v4 = srow[tid];
    float v[4] = {v4.x, v4.y, v4.z, v4.w};

    float mx = fmaxf(fmaxf(v[0], v[1]), fmaxf(v[2], v[3]));
    mx = blockRedMax(mx, red);

    float e[4], s = 0.f;
#pragma unroll
    for (int i = 0; i < 4; i++) { e[i] = expf(v[i] - mx); s += e[i]; }
    s = blockRedSum(s, red);
    const float inv = 1.f / s;

    float mk[4];
#pragma unroll
    for (int i = 0; i < 4; i++) {
        float a = e[i] * inv;
        mk[i] = (a >= alpha) ? a : 0.f;
    }
    mrow[tid] = make_float4(mk[0], mk[1], mk[2], mk[3]);

    float mx2 = fmaxf(fmaxf(mk[0], mk[1]), fmaxf(mk[2], mk[3]));
    mx2 = blockRedMax(mx2, red);

    float e2[4], s2 = 0.f;
#pragma unroll
    for (int i = 0; i < 4; i++) { e2[i] = expf(mk[i] - mx2); s2 += e2[i]; }
    s2 = blockRedSum(s2, red);
    const float inv2 = 1.f / s2;

    srow[tid] = make_float4(e2[0] * inv2, e2[1] * inv2, e2[2] * inv2, e2[3] * inv2);
}

// ---------------- out = LayerNorm(a + b) * g + beta ---------------------------
__global__ void __launch_bounds__(256)
add_ln_k(const float* __restrict__ A, const float* __restrict__ Bsrc,
         const float* __restrict__ g, const float* __restrict__ bet,
         float* __restrict__ out)
{
    __shared__ float red[32];
    const long row = blockIdx.x;
    const int tid = threadIdx.x;

    float4 a4 = reinterpret_cast<const float4*>(A    + row * 1024)[tid];
    float4 b4 = reinterpret_cast<const float4*>(Bsrc + row * 1024)[tid];
    float x[4] = {a4.x + b4.x, a4.y + b4.y, a4.z + b4.z, a4.w + b4.w};

    float s = x[0] + x[1] + x[2] + x[3];
    s = blockRedSum(s, red);
    const float mu = s * (1.f / 1024.f);

    float vs = 0.f;
#pragma unroll
    for (int i = 0; i < 4; i++) { float d = x[i] - mu; vs += d * d; }
    vs = blockRedSum(vs, red);
    const float inv = rsqrtf(vs * (1.f / 1024.f) + 1e-5f);

    float4 g4 = reinterpret_cast<const float4*>(g)[tid];
    float4 e4 = reinterpret_cast<const float4*>(bet)[tid];
    float4 o;
    o.x = (x[0] - mu) * inv * g4.x + e4.x;
    o.y = (x[1] - mu) * inv * g4.y + e4.y;
    o.z = (x[2] - mu) * inv * g4.z + e4.z;
    o.w = (x[3] - mu) * inv * g4.w + e4.w;
    reinterpret_cast<float4*>(out + row * 1024)[tid] = o;
}

// ---------------- driver ------------------------------------------------------
extern "C" void kernel_launch(void* const* d_in, const int* in_sizes, int n_in,
                              void* d_out, int out_size)
{
    const float* base   = (const float*)d_in[0];
    const float* fusion = (const float*)d_in[1];
    const float* Wq     = (const float*)d_in[2];
    const float* Wk     = (const float*)d_in[3];
    const float* Wv     = (const float*)d_in[4];
    const float* Wo     = (const float*)d_in[5];
    const float* g1     = (const float*)d_in[6];
    const float* b1     = (const float*)d_in[7];
    const float* g2     = (const float*)d_in[8];
    const float* b2     = (const float*)d_in[9];
    const float* fc1_w  = (const float*)d_in[10];
    const float* fc1_b  = (const float*)d_in[11];
    const float* fc2_w  = (const float*)d_in[12];
    const float* fc2_b  = (const float*)d_in[13];
    const float* rw     = (const float*)d_in[14];
    const float* rbias  = (const float*)d_in[15];
    const float* alphap = (const float*)d_in[16];

    float* outf = (float*)d_out;                       // final [8,1024,1024]
    float* outm = outf + (long)B_ * TQ_ * D_;          // masked [8,16,1024,1024]

    float *q, *k, *v, *sc, *ao, *x;
    cudaGetSymbolAddress((void**)&q,  g_q);
    cudaGetSymbolAddress((void**)&k,  g_k);
    cudaGetSymbolAddress((void**)&v,  g_v);
    cudaGetSymbolAddress((void**)&sc, g_sc);
    cudaGetSymbolAddress((void**)&ao, g_ao);
    cudaGetSymbolAddress((void**)&x,  g_x);

    const dim3 blk(256);
    const dim3 gBig(D_ / 128, (B_ * TQ_) / 128, 1);    // 8 x 64

    // Q/K/V projections (tf32)
    gemm_nt_tf32<<<gBig, blk>>>(base,   Wq, q, D_, D_, D_, D_, 0,0,0,0,0,0, 1.f, nullptr, 0);
    gemm_nt_tf32<<<gBig, blk>>>(fusion, Wk, k, D_, D_, D_, D_, 0,0,0,0,0,0, 1.f, nullptr, 0);
    gemm_nt_tf32<<<gBig, blk>>>(fusion, Wv, v, D_, D_, D_, D_, 0,0,0,0,0,0, 1.f, nullptr, 0);

    // scores = Q K^T / sqrt(HD)  per (b,h)
    gemm_nt_tf32<<<dim3(TK_ / 128, TQ_ / 128, B_ * H_), blk>>>(
        q, k, sc, HD_, D_, D_, TK_,
        (long)TQ_ * D_, HD_, (long)TK_ * D_, HD_,
        (long)H_ * TQ_ * TK_, (long)TQ_ * TK_,
        0.125f, nullptr, 0);

    // softmax -> mask (write masked output) -> softmax2 (in place)
    softmax_mask_k<<<B_ * H_ * TQ_, blk>>>(sc, outm, alphap);

    // attn2 @ V -> merged heads (tf32)
    attn_v_tf32<<<dim3(1, TQ_ / 128, B_ * H_), blk>>>(sc, v, ao);

    // O projection (reuse g_q)
    gemm_nt_tf32<<<gBig, blk>>>(ao, Wo, q, D_, D_, D_, D_, 0,0,0,0,0,0, 1.f, nullptr, 0);

    // x = LN(base + proj)
    add_ln_k<<<B_ * TQ_, blk>>>(base, q, g1, b1, x);

    // FFN: h1 = silu(x fc1^T + b)  (reuse g_k), ff = silu(h1 fc2^T + b) (reuse g_v)
    gemm_nt_tf32<<<gBig, blk>>>(x, fc1_w, k, D_, D_, D_, D_, 0,0,0,0,0,0, 1.f, fc1_b, 2);
    gemm_nt_tf32<<<gBig, blk>>>(k, fc2_w, v, D_, D_, D_, D_, 0,0,0,0,0,0, 1.f, fc2_b, 2);

    // y = LN(x + ff)  (reuse g_q)
    add_ln_k<<<B_ * TQ_, blk>>>(x, v, g2, b2, q);

    // final = y rw^T + rb
    gemm_nt_tf32<<<gBig, blk>>>(q, rw, outf, D_, D_, D_, D_, 0,0,0,0,0,0, 1.f, rbias, 1);
}